// round 13
// baseline (speedup 1.0000x reference)
#include <cuda_runtime.h>
#include <cuda_bf16.h>
#include <cstdint>

#define NN 50000
#define EE 800000
#define FIN 128
#define FH 96
#define FOUT 64
#define BN_EPS 1e-5f
#define SCAN_NB 49            // ceil(50000/1024) -- scan-participating blocks
#define GRID_NB 148           // one block per SM; all resident -> barrier safe

// ----------------------------------------------------------------------------
// Device scratch (static; no cudaMalloc anywhere).
// build_graph is fully self-contained: leaves g_deg/g_cnt/g_scanstate and the
// barrier state zeroed for the next call. First call sees load-time zeros.
// ----------------------------------------------------------------------------
__device__ float g_deg[NN];
__device__ float g_dis[NN];
__device__ int   g_cnt[NN];
__device__ int   g_cursor[NN];
__device__ unsigned long long g_scanstate[SCAN_NB];
__device__ int   g_bar_count;
__device__ volatile int g_bar_sense;
__device__ int   g_rowptr[NN + 1];
__device__ int   g_src[EE];
__device__ float g_norm[EE];
__device__ uint32_t g_xwb[(size_t)NN * FH / 2];   // GEMM output, bf16x2 packed
__device__ float g_h[(size_t)NN * FH];            // activation buffer (fp32)
__device__ float g_sc[3][FH];
__device__ float g_sh[3][FH];

// ----------------------------------------------------------------------------
// Self-resetting sense-reversing grid barrier (all GRID_NB blocks resident).
// ----------------------------------------------------------------------------
__device__ __forceinline__ void grid_barrier(int* sense_local) {
    __syncthreads();
    if (threadIdx.x == 0) {
        int s = *sense_local ^ 1;
        *sense_local = s;
        __threadfence();
        if (atomicAdd(&g_bar_count, 1) == GRID_NB - 1) {
            g_bar_count = 0;
            __threadfence();
            g_bar_sense = s;
        } else {
            while (g_bar_sense != s) __nanosleep(64);
        }
    }
    __syncthreads();
}

// ----------------------------------------------------------------------------
// Fused graph build, 148 blocks x 1024 threads (full chip on edge phases).
// ----------------------------------------------------------------------------
#define FLAG_AGG (1ULL << 62)
#define FLAG_INC (2ULL << 62)
#define VAL_MASK 0xffffffffULL

__global__ void __launch_bounds__(1024, 1)
build_graph(const int* __restrict__ ei, const float* __restrict__ ew,
            const float* g1, const float* be1, const float* m1, const float* v1, const float* b1,
            const float* g2, const float* be2, const float* m2, const float* v2, const float* b2,
            const float* b3) {
    int tid = threadIdx.x, bid = blockIdx.x;
    int gid = bid * 1024 + tid;
    const int GSTR = GRID_NB * 1024;
    int sense = 0;

    // Folded affine params (block 0, disjoint thread ranges)
    if (bid == 0) {
        if (tid < FH) {
            int f = tid;
            float a = g1[f] * rsqrtf(v1[f] + BN_EPS);
            g_sc[0][f] = a;
            g_sh[0][f] = (b1[f] - m1[f]) * a + be1[f];
        } else if (tid >= 128 && tid < 128 + FH) {
            int f = tid - 128;
            float a = g2[f] * rsqrtf(v2[f] + BN_EPS);
            g_sc[1][f] = a;
            g_sh[1][f] = (b2[f] - m2[f]) * a + be2[f];
        } else if (tid >= 256 && tid < 256 + FOUT) {
            int f = tid - 256;
            g_sc[2][f] = 1.0f;
            g_sh[2][f] = b3[f];
        }
    }

    // Phase A: degree accumulation, full chip
    for (int e = gid; e < EE; e += GSTR) {
        int c = ei[EE + e];
        atomicAdd(&g_deg[c], ew[e]);
        atomicAdd(&g_cnt[c], 1);
    }
    grid_barrier(&sense);

    // Phase B: blocks 0..48 do the node scan; others wait at the barrier
    if (bid < SCAN_NB) {
        __shared__ int sh[1024];
        __shared__ int s_prefix;
        int i = bid * 1024 + tid;
        int v = (i < NN) ? g_cnt[i] : 0;
        sh[tid] = v;
        __syncthreads();
#pragma unroll
        for (int off = 1; off < 1024; off <<= 1) {
            int t = (tid >= off) ? sh[tid - off] : 0;
            __syncthreads();
            sh[tid] += t;
            __syncthreads();
        }
        int total = sh[1023];
        if (tid == 0) {
            if (bid == 0) {
                s_prefix = 0;
                atomicExch(&g_scanstate[0], FLAG_INC | (unsigned long long)total);
                g_rowptr[NN] = EE;
            } else {
                atomicExch(&g_scanstate[bid], FLAG_AGG | (unsigned long long)total);
                int p = bid - 1;
                long long prefix = 0;
                while (true) {
                    unsigned long long s = *(volatile unsigned long long*)&g_scanstate[p];
                    unsigned long long flag = s & (3ULL << 62);
                    if (flag == FLAG_INC) { prefix += (long long)(s & VAL_MASK); break; }
                    if (flag == FLAG_AGG) { prefix += (long long)(s & VAL_MASK); --p; }
                    else __nanosleep(32);
                }
                atomicExch(&g_scanstate[bid], FLAG_INC | (unsigned long long)(prefix + total));
                s_prefix = (int)prefix;
            }
        }
        __syncthreads();
        if (i < NN) {
            g_rowptr[i] = s_prefix + sh[tid] - v;
            g_dis[i] = rsqrtf(g_deg[i] + 1.0f);   // self-loop weight 1 => deg>0
            g_cursor[i] = 0;                       // ready for phase C
        }
    }
    grid_barrier(&sense);

    // Phase C: fill CSR, full chip + restore zero-state
    for (int e = gid; e < EE; e += GSTR) {
        int r = ei[e];
        int c = ei[EE + e];
        float nrm = g_dis[r] * ew[e] * g_dis[c];
        int pos = g_rowptr[c] + atomicAdd(&g_cursor[c], 1);
        g_src[pos] = r;
        g_norm[pos] = nrm;
    }
    if (bid < SCAN_NB) {
        int i = bid * 1024 + tid;
        if (i < NN) { g_deg[i] = 0.f; g_cnt[i] = 0; }
        if (tid == 0) g_scanstate[bid] = 0ULL;
    }
}

// ----------------------------------------------------------------------------
// tf32 tensor-core GEMM with cp.async double buffering.
// BM=128, BK=16, 256 threads (4 M-warps x 2 N-warps), 3 blocks/SM.
// Output written as packed bf16x2 into g_xwb.
// ----------------------------------------------------------------------------
__device__ __forceinline__ float f2tf32(float x) {
    uint32_t r;
    asm("cvt.rna.tf32.f32 %0, %1;" : "=r"(r) : "f"(x));
    float out;
    asm("mov.b32 %0, %1;" : "=f"(out) : "r"(r));
    return out;
}

__device__ __forceinline__ uint32_t packbf(float lo, float hi) {
    __nv_bfloat162 h = __floats2bfloat162_rn(lo, hi);   // .x = lo (low half)
    return *reinterpret_cast<uint32_t*>(&h);
}

__device__ __forceinline__ void cp_async16(uint32_t saddr, const void* gptr) {
    asm volatile("cp.async.cg.shared.global [%0], [%1], 16;" :: "r"(saddr), "l"(gptr));
}
__device__ __forceinline__ void cp_commit() {
    asm volatile("cp.async.commit_group;");
}
template <int N>
__device__ __forceinline__ void cp_wait() {
    asm volatile("cp.async.wait_group %0;" :: "n"(N));
}

template <int KDIM, int BN, bool FROM_H>
__global__ void __launch_bounds__(256, 3) gemm_tc(const float* __restrict__ Xext,
                                                  const float* __restrict__ W) {
    constexpr int BM = 128, BK = 16;
    constexpr int WN = BN / 2;          // 48 or 32
    constexpr int NF = WN / 8;          // 6 or 4
    constexpr int KT = KDIM / BK;       // 8 or 6
    constexpr int STR = BK + 4;         // 20 floats
    constexpr int KD4 = KDIM / 4;
    constexpr int NBQ = BN * (BK / 4);  // B float4s per tile

    const float* __restrict__ X = FROM_H ? (const float*)g_h : Xext;

    __shared__ float As[2][BM][STR];
    __shared__ float Bs[2][BN][STR];

    int tid = threadIdx.x;
    int wid = tid >> 5, lane = tid & 31;
    int wm = wid & 3, wn = wid >> 2;
    int g = lane >> 2, tig = lane & 3;
    int row0 = blockIdx.x * BM;
    int m0 = wm * 32;
    int n0 = wn * WN;

    float acc[2][NF][4];
#pragma unroll
    for (int mi = 0; mi < 2; ++mi)
#pragma unroll
        for (int ni = 0; ni < NF; ++ni)
#pragma unroll
            for (int c = 0; c < 4; ++c) acc[mi][ni][c] = 0.f;

    const float4* __restrict__ X4 = reinterpret_cast<const float4*>(X);
    const float4* __restrict__ W4 = reinterpret_cast<const float4*>(W);

    auto issue_tile = [&](int kt, int buf) {
        int kb4 = kt * (BK / 4);
#pragma unroll
        for (int t = 0; t < 2; ++t) {
            int idx = tid + t * 256;           // 0..511
            int m = idx >> 2, kq = idx & 3;
            int r = row0 + m;
            if (r < NN) {
                uint32_t dst = (uint32_t)__cvta_generic_to_shared(&As[buf][m][kq * 4]);
                cp_async16(dst, &X4[(size_t)r * KD4 + kb4 + kq]);
            }
        }
#pragma unroll
        for (int t = 0; t < (NBQ + 255) / 256; ++t) {
            int idx = tid + t * 256;
            if (idx < NBQ) {
                int f = idx >> 2, kq = idx & 3;
                uint32_t dst = (uint32_t)__cvta_generic_to_shared(&Bs[buf][f][kq * 4]);
                cp_async16(dst, &W4[(size_t)f * KD4 + kb4 + kq]);
            }
        }
    };

    issue_tile(0, 0);
    cp_commit();

    for (int kt = 0; kt < KT; ++kt) {
        int cur = kt & 1;
        if (kt + 1 < KT) {
            issue_tile(kt + 1, cur ^ 1);
            cp_commit();
            cp_wait<1>();
        } else {
            cp_wait<0>();
        }
        __syncthreads();

#pragma unroll
        for (int kf = 0; kf < BK / 8; ++kf) {
            int kb = kf * 8;
            uint32_t a[2][4];
#pragma unroll
            for (int mi = 0; mi < 2; ++mi) {
                int mb = m0 + mi * 16;
                a[mi][0] = __float_as_uint(f2tf32(As[cur][mb + g][kb + tig]));
                a[mi][1] = __float_as_uint(f2tf32(As[cur][mb + g + 8][kb + tig]));
                a[mi][2] = __float_as_uint(f2tf32(As[cur][mb + g][kb + tig + 4]));
                a[mi][3] = __float_as_uint(f2tf32(As[cur][mb + g + 8][kb + tig + 4]));
            }
            uint32_t b[NF][2];
#pragma unroll
            for (int ni = 0; ni < NF; ++ni) {
                int nb = n0 + ni * 8;
                b[ni][0] = __float_as_uint(f2tf32(Bs[cur][nb + g][kb + tig]));
                b[ni][1] = __float_as_uint(f2tf32(Bs[cur][nb + g][kb + tig + 4]));
            }
#pragma unroll
            for (int mi = 0; mi < 2; ++mi)
#pragma unroll
                for (int ni = 0; ni < NF; ++ni) {
                    asm volatile(
                        "mma.sync.aligned.m16n8k8.row.col.f32.tf32.tf32.f32 "
                        "{%0,%1,%2,%3},{%4,%5,%6,%7},{%8,%9},{%0,%1,%2,%3};"
                        : "+f"(acc[mi][ni][0]), "+f"(acc[mi][ni][1]),
                          "+f"(acc[mi][ni][2]), "+f"(acc[mi][ni][3])
                        : "r"(a[mi][0]), "r"(a[mi][1]), "r"(a[mi][2]), "r"(a[mi][3]),
                          "r"(b[ni][0]), "r"(b[ni][1]));
                }
        }
        __syncthreads();
    }

    // Epilogue: each acc quad covers rows (g, g+8) x cols (2*tig, 2*tig+1).
    // Pack the column pair to bf16x2 and store one uint32.
#pragma unroll
    for (int mi = 0; mi < 2; ++mi) {
        int r0 = row0 + m0 + mi * 16 + g;
        int r1 = r0 + 8;
#pragma unroll
        for (int ni = 0; ni < NF; ++ni) {
            int c = n0 + ni * 8 + tig * 2;
            if (r0 < NN)
                g_xwb[(size_t)r0 * (BN / 2) + (c >> 1)] = packbf(acc[mi][ni][0], acc[mi][ni][1]);
            if (r1 < NN)
                g_xwb[(size_t)r1 * (BN / 2) + (c >> 1)] = packbf(acc[mi][ni][2], acc[mi][ni][3]);
        }
    }
}

// ----------------------------------------------------------------------------
// CSR aggregation over bf16 features: one warp/node, lanes 0..F/8-1 each
// hold 8 features (one uint4 = 4x bf16x2). fp32 accumulation. Dual edge
// unroll for ILP. 512-thread blocks.
// ----------------------------------------------------------------------------
__device__ __forceinline__ void bf16_fma8(float* acc, uint4 v, float n) {
    const __nv_bfloat162* p = reinterpret_cast<const __nv_bfloat162*>(&v);
#pragma unroll
    for (int q = 0; q < 4; ++q) {
        float2 f = __bfloat1622float2(p[q]);
        acc[2 * q]     += n * f.x;
        acc[2 * q + 1] += n * f.y;
    }
}

template <int F, bool RELU, bool TO_H, int LAYER>
__global__ void aggregate(float* __restrict__ outExt) {
    constexpr int LANES = F / 8;    // 12 (F=96) or 8 (F=64)
    int warp = blockIdx.x * (blockDim.x >> 5) + (threadIdx.x >> 5);
    if (warp >= NN) return;
    int lane = threadIdx.x & 31;
    const uint4* __restrict__ xwb = reinterpret_cast<const uint4*>(g_xwb);
    float* __restrict__ out = TO_H ? (float*)g_h : outExt;
    bool active = lane < LANES;

    float acc[8];
#pragma unroll
    for (int q = 0; q < 8; ++q) acc[q] = 0.f;

    int s = g_rowptr[warp], t = g_rowptr[warp + 1];
    for (int base = s; base < t; base += 32) {
        int idx = base + lane;
        int src = 0; float nrm = 0.f;
        if (idx < t) { src = g_src[idx]; nrm = g_norm[idx]; }
        int cnt = min(32, t - base);
        int j = 0;
        for (; j + 1 < cnt; j += 2) {
            int s0 = __shfl_sync(0xffffffffu, src, j);
            float n0 = __shfl_sync(0xffffffffu, nrm, j);
            int s1 = __shfl_sync(0xffffffffu, src, j + 1);
            float n1 = __shfl_sync(0xffffffffu, nrm, j + 1);
            if (active) {
                uint4 v0 = xwb[(size_t)s0 * LANES + lane];
                uint4 v1 = xwb[(size_t)s1 * LANES + lane];
                bf16_fma8(acc, v0, n0);
                bf16_fma8(acc, v1, n1);
            }
        }
        if (j < cnt) {
            int s0 = __shfl_sync(0xffffffffu, src, j);
            float n0 = __shfl_sync(0xffffffffu, nrm, j);
            if (active) {
                uint4 v0 = xwb[(size_t)s0 * LANES + lane];
                bf16_fma8(acc, v0, n0);
            }
        }
    }
    float d = g_dis[warp];
    float sn = d * d;
    if (active) {
        uint4 v = xwb[(size_t)warp * LANES + lane];
        bf16_fma8(acc, v, sn);

        int f0 = lane * 8;
        float r[8];
#pragma unroll
        for (int q = 0; q < 8; ++q) {
            float val = acc[q] * g_sc[LAYER][f0 + q] + g_sh[LAYER][f0 + q];
            if (RELU) val = fmaxf(val, 0.f);
            r[q] = val;
        }
        float4* o4 = reinterpret_cast<float4*>(&out[(size_t)warp * F + f0]);
        o4[0] = make_float4(r[0], r[1], r[2], r[3]);
        o4[1] = make_float4(r[4], r[5], r[6], r[7]);
    }
}

// ----------------------------------------------------------------------------
// Launch — 7 kernel launches, graph-capturable.
// ----------------------------------------------------------------------------
extern "C" void kernel_launch(void* const* d_in, const int* in_sizes, int n_in,
                              void* d_out, int out_size) {
    const float* x   = (const float*)d_in[0];
    const int*   ei  = (const int*)d_in[1];       // int32 (JAX x64 disabled)
    const float* ew  = (const float*)d_in[2];
    const float* W1  = (const float*)d_in[3];
    const float* b1  = (const float*)d_in[4];
    const float* W2  = (const float*)d_in[5];
    const float* b2  = (const float*)d_in[6];
    const float* W3  = (const float*)d_in[7];
    const float* b3  = (const float*)d_in[8];
    const float* g1  = (const float*)d_in[9];
    const float* be1 = (const float*)d_in[10];
    const float* m1  = (const float*)d_in[11];
    const float* v1  = (const float*)d_in[12];
    const float* g2  = (const float*)d_in[13];
    const float* be2 = (const float*)d_in[14];
    const float* m2  = (const float*)d_in[15];
    const float* v2  = (const float*)d_in[16];
    float* out = (float*)d_out;

    build_graph<<<GRID_NB, 1024>>>(ei, ew,
                                   g1, be1, m1, v1, b1,
                                   g2, be2, m2, v2, b2, b3);

    const int gemmBlocks = (NN + 127) / 128;   // 391
    const int aggBlocks  = (NN + 15) / 16;     // 16 warps/block of 512

    gemm_tc<FIN, FH, false><<<gemmBlocks, 256>>>(x, W1);
    aggregate<FH, true, true, 0><<<aggBlocks, 512>>>(nullptr);

    gemm_tc<FH, FH, true><<<gemmBlocks, 256>>>(nullptr, W2);
    aggregate<FH, true, true, 1><<<aggBlocks, 512>>>(nullptr);

    gemm_tc<FH, FOUT, true><<<gemmBlocks, 256>>>(nullptr, W3);
    aggregate<FOUT, false, false, 2><<<aggBlocks, 512>>>(out);
}

// round 14
// speedup vs baseline: 1.1808x; 1.1808x over previous
#include <cuda_runtime.h>
#include <cuda_bf16.h>
#include <cstdint>

#define NN 50000
#define EE 800000
#define FIN 128
#define FH 96
#define FOUT 64
#define BN_EPS 1e-5f
#define SCAN_NB 49            // ceil(50000/1024) -- scan-participating blocks
#define GRID_NB 148           // one block per SM; all resident -> barrier safe

// ----------------------------------------------------------------------------
// Device scratch (static; no cudaMalloc anywhere).
// build_graph is fully self-contained: leaves g_deg/g_cnt/g_scanstate and the
// barrier state zeroed for the next call. First call sees load-time zeros.
// ----------------------------------------------------------------------------
__device__ float g_deg[NN];
__device__ float g_dis[NN];
__device__ int   g_cnt[NN];
__device__ int   g_cursor[NN];
__device__ unsigned long long g_scanstate[SCAN_NB];
__device__ int   g_bar_count;
__device__ volatile int g_bar_sense;
__device__ int   g_rowptr[NN + 1];
__device__ int   g_src[EE];
__device__ float g_norm[EE];
__device__ uint32_t g_xwb[(size_t)NN * FH / 2];   // GEMM output, bf16x2 packed
__device__ float g_h[(size_t)NN * FH];            // activation buffer (fp32)
__device__ float g_sc[3][FH];
__device__ float g_sh[3][FH];

// ----------------------------------------------------------------------------
// Self-resetting sense-reversing grid barrier (all GRID_NB blocks resident).
// ----------------------------------------------------------------------------
__device__ __forceinline__ void grid_barrier(int* sense_local) {
    __syncthreads();
    if (threadIdx.x == 0) {
        int s = *sense_local ^ 1;
        *sense_local = s;
        __threadfence();
        if (atomicAdd(&g_bar_count, 1) == GRID_NB - 1) {
            g_bar_count = 0;
            __threadfence();
            g_bar_sense = s;
        } else {
            while (g_bar_sense != s) __nanosleep(64);
        }
    }
    __syncthreads();
}

// ----------------------------------------------------------------------------
// Fused graph build, 148 blocks x 1024 threads (full chip on edge phases).
// ----------------------------------------------------------------------------
#define FLAG_AGG (1ULL << 62)
#define FLAG_INC (2ULL << 62)
#define VAL_MASK 0xffffffffULL

__global__ void __launch_bounds__(1024, 1)
build_graph(const int* __restrict__ ei, const float* __restrict__ ew,
            const float* g1, const float* be1, const float* m1, const float* v1, const float* b1,
            const float* g2, const float* be2, const float* m2, const float* v2, const float* b2,
            const float* b3) {
    int tid = threadIdx.x, bid = blockIdx.x;
    int gid = bid * 1024 + tid;
    const int GSTR = GRID_NB * 1024;
    int sense = 0;

    // Folded affine params (block 0, disjoint thread ranges)
    if (bid == 0) {
        if (tid < FH) {
            int f = tid;
            float a = g1[f] * rsqrtf(v1[f] + BN_EPS);
            g_sc[0][f] = a;
            g_sh[0][f] = (b1[f] - m1[f]) * a + be1[f];
        } else if (tid >= 128 && tid < 128 + FH) {
            int f = tid - 128;
            float a = g2[f] * rsqrtf(v2[f] + BN_EPS);
            g_sc[1][f] = a;
            g_sh[1][f] = (b2[f] - m2[f]) * a + be2[f];
        } else if (tid >= 256 && tid < 256 + FOUT) {
            int f = tid - 256;
            g_sc[2][f] = 1.0f;
            g_sh[2][f] = b3[f];
        }
    }

    // Phase A: degree accumulation, full chip
    for (int e = gid; e < EE; e += GSTR) {
        int c = ei[EE + e];
        atomicAdd(&g_deg[c], ew[e]);
        atomicAdd(&g_cnt[c], 1);
    }
    grid_barrier(&sense);

    // Phase B: blocks 0..48 do the node scan; others wait at the barrier
    if (bid < SCAN_NB) {
        __shared__ int sh[1024];
        __shared__ int s_prefix;
        int i = bid * 1024 + tid;
        int v = (i < NN) ? g_cnt[i] : 0;
        sh[tid] = v;
        __syncthreads();
#pragma unroll
        for (int off = 1; off < 1024; off <<= 1) {
            int t = (tid >= off) ? sh[tid - off] : 0;
            __syncthreads();
            sh[tid] += t;
            __syncthreads();
        }
        int total = sh[1023];
        if (tid == 0) {
            if (bid == 0) {
                s_prefix = 0;
                atomicExch(&g_scanstate[0], FLAG_INC | (unsigned long long)total);
                g_rowptr[NN] = EE;
            } else {
                atomicExch(&g_scanstate[bid], FLAG_AGG | (unsigned long long)total);
                int p = bid - 1;
                long long prefix = 0;
                while (true) {
                    unsigned long long s = *(volatile unsigned long long*)&g_scanstate[p];
                    unsigned long long flag = s & (3ULL << 62);
                    if (flag == FLAG_INC) { prefix += (long long)(s & VAL_MASK); break; }
                    if (flag == FLAG_AGG) { prefix += (long long)(s & VAL_MASK); --p; }
                    else __nanosleep(32);
                }
                atomicExch(&g_scanstate[bid], FLAG_INC | (unsigned long long)(prefix + total));
                s_prefix = (int)prefix;
            }
        }
        __syncthreads();
        if (i < NN) {
            g_rowptr[i] = s_prefix + sh[tid] - v;
            g_dis[i] = rsqrtf(g_deg[i] + 1.0f);   // self-loop weight 1 => deg>0
            g_cursor[i] = 0;                       // ready for phase C
        }
    }
    grid_barrier(&sense);

    // Phase C: fill CSR, full chip + restore zero-state
    for (int e = gid; e < EE; e += GSTR) {
        int r = ei[e];
        int c = ei[EE + e];
        float nrm = g_dis[r] * ew[e] * g_dis[c];
        int pos = g_rowptr[c] + atomicAdd(&g_cursor[c], 1);
        g_src[pos] = r;
        g_norm[pos] = nrm;
    }
    if (bid < SCAN_NB) {
        int i = bid * 1024 + tid;
        if (i < NN) { g_deg[i] = 0.f; g_cnt[i] = 0; }
        if (tid == 0) g_scanstate[bid] = 0ULL;
    }
}

// ----------------------------------------------------------------------------
// tf32 tensor-core GEMM with cp.async double buffering.
// BM=128, BK=16, 256 threads (4 M-warps x 2 N-warps), 3 blocks/SM.
// Output written as packed bf16x2 into g_xwb.
// ----------------------------------------------------------------------------
__device__ __forceinline__ float f2tf32(float x) {
    uint32_t r;
    asm("cvt.rna.tf32.f32 %0, %1;" : "=r"(r) : "f"(x));
    float out;
    asm("mov.b32 %0, %1;" : "=f"(out) : "r"(r));
    return out;
}

__device__ __forceinline__ uint32_t packbf(float lo, float hi) {
    __nv_bfloat162 h = __floats2bfloat162_rn(lo, hi);   // .x = lo (low half)
    return *reinterpret_cast<uint32_t*>(&h);
}

__device__ __forceinline__ void cp_async16(uint32_t saddr, const void* gptr) {
    asm volatile("cp.async.cg.shared.global [%0], [%1], 16;" :: "r"(saddr), "l"(gptr));
}
__device__ __forceinline__ void cp_commit() {
    asm volatile("cp.async.commit_group;");
}
template <int N>
__device__ __forceinline__ void cp_wait() {
    asm volatile("cp.async.wait_group %0;" :: "n"(N));
}

template <int KDIM, int BN, bool FROM_H>
__global__ void __launch_bounds__(256, 3) gemm_tc(const float* __restrict__ Xext,
                                                  const float* __restrict__ W) {
    constexpr int BM = 128, BK = 16;
    constexpr int WN = BN / 2;          // 48 or 32
    constexpr int NF = WN / 8;          // 6 or 4
    constexpr int KT = KDIM / BK;       // 8 or 6
    constexpr int STR = BK + 4;         // 20 floats
    constexpr int KD4 = KDIM / 4;
    constexpr int NBQ = BN * (BK / 4);  // B float4s per tile

    const float* __restrict__ X = FROM_H ? (const float*)g_h : Xext;

    __shared__ float As[2][BM][STR];
    __shared__ float Bs[2][BN][STR];

    int tid = threadIdx.x;
    int wid = tid >> 5, lane = tid & 31;
    int wm = wid & 3, wn = wid >> 2;
    int g = lane >> 2, tig = lane & 3;
    int row0 = blockIdx.x * BM;
    int m0 = wm * 32;
    int n0 = wn * WN;

    float acc[2][NF][4];
#pragma unroll
    for (int mi = 0; mi < 2; ++mi)
#pragma unroll
        for (int ni = 0; ni < NF; ++ni)
#pragma unroll
            for (int c = 0; c < 4; ++c) acc[mi][ni][c] = 0.f;

    const float4* __restrict__ X4 = reinterpret_cast<const float4*>(X);
    const float4* __restrict__ W4 = reinterpret_cast<const float4*>(W);

    auto issue_tile = [&](int kt, int buf) {
        int kb4 = kt * (BK / 4);
#pragma unroll
        for (int t = 0; t < 2; ++t) {
            int idx = tid + t * 256;           // 0..511
            int m = idx >> 2, kq = idx & 3;
            int r = row0 + m;
            if (r < NN) {
                uint32_t dst = (uint32_t)__cvta_generic_to_shared(&As[buf][m][kq * 4]);
                cp_async16(dst, &X4[(size_t)r * KD4 + kb4 + kq]);
            }
        }
#pragma unroll
        for (int t = 0; t < (NBQ + 255) / 256; ++t) {
            int idx = tid + t * 256;
            if (idx < NBQ) {
                int f = idx >> 2, kq = idx & 3;
                uint32_t dst = (uint32_t)__cvta_generic_to_shared(&Bs[buf][f][kq * 4]);
                cp_async16(dst, &W4[(size_t)f * KD4 + kb4 + kq]);
            }
        }
    };

    issue_tile(0, 0);
    cp_commit();

    for (int kt = 0; kt < KT; ++kt) {
        int cur = kt & 1;
        if (kt + 1 < KT) {
            issue_tile(kt + 1, cur ^ 1);
            cp_commit();
            cp_wait<1>();
        } else {
            cp_wait<0>();
        }
        __syncthreads();

#pragma unroll
        for (int kf = 0; kf < BK / 8; ++kf) {
            int kb = kf * 8;
            uint32_t a[2][4];
#pragma unroll
            for (int mi = 0; mi < 2; ++mi) {
                int mb = m0 + mi * 16;
                a[mi][0] = __float_as_uint(f2tf32(As[cur][mb + g][kb + tig]));
                a[mi][1] = __float_as_uint(f2tf32(As[cur][mb + g + 8][kb + tig]));
                a[mi][2] = __float_as_uint(f2tf32(As[cur][mb + g][kb + tig + 4]));
                a[mi][3] = __float_as_uint(f2tf32(As[cur][mb + g + 8][kb + tig + 4]));
            }
            uint32_t b[NF][2];
#pragma unroll
            for (int ni = 0; ni < NF; ++ni) {
                int nb = n0 + ni * 8;
                b[ni][0] = __float_as_uint(f2tf32(Bs[cur][nb + g][kb + tig]));
                b[ni][1] = __float_as_uint(f2tf32(Bs[cur][nb + g][kb + tig + 4]));
            }
#pragma unroll
            for (int mi = 0; mi < 2; ++mi)
#pragma unroll
                for (int ni = 0; ni < NF; ++ni) {
                    asm volatile(
                        "mma.sync.aligned.m16n8k8.row.col.f32.tf32.tf32.f32 "
                        "{%0,%1,%2,%3},{%4,%5,%6,%7},{%8,%9},{%0,%1,%2,%3};"
                        : "+f"(acc[mi][ni][0]), "+f"(acc[mi][ni][1]),
                          "+f"(acc[mi][ni][2]), "+f"(acc[mi][ni][3])
                        : "r"(a[mi][0]), "r"(a[mi][1]), "r"(a[mi][2]), "r"(a[mi][3]),
                          "r"(b[ni][0]), "r"(b[ni][1]));
                }
        }
        __syncthreads();
    }

    // Epilogue: pack column pairs to bf16x2, one uint32 store each.
#pragma unroll
    for (int mi = 0; mi < 2; ++mi) {
        int r0 = row0 + m0 + mi * 16 + g;
        int r1 = r0 + 8;
#pragma unroll
        for (int ni = 0; ni < NF; ++ni) {
            int c = n0 + ni * 8 + tig * 2;
            if (r0 < NN)
                g_xwb[(size_t)r0 * (BN / 2) + (c >> 1)] = packbf(acc[mi][ni][0], acc[mi][ni][1]);
            if (r1 < NN)
                g_xwb[(size_t)r1 * (BN / 2) + (c >> 1)] = packbf(acc[mi][ni][2], acc[mi][ni][3]);
        }
    }
}

// ----------------------------------------------------------------------------
// CSR aggregation over bf16 features. One warp/node. Lanes 0..F/4-1 each
// hold 4 features (one uint2 = 2x bf16x2). No shfl: edge indices/weights are
// warp-uniform broadcast loads. Unroll-4 over edges -> 4 gathers in flight.
// fp32 accumulation. 512-thread blocks.
// ----------------------------------------------------------------------------
__device__ __forceinline__ void bf16_fma4(float* acc, uint2 v, float n) {
    __nv_bfloat162 p0 = *reinterpret_cast<__nv_bfloat162*>(&v.x);
    __nv_bfloat162 p1 = *reinterpret_cast<__nv_bfloat162*>(&v.y);
    float2 f0 = __bfloat1622float2(p0);
    float2 f1 = __bfloat1622float2(p1);
    acc[0] += n * f0.x;
    acc[1] += n * f0.y;
    acc[2] += n * f1.x;
    acc[3] += n * f1.y;
}

template <int F, bool RELU, bool TO_H, int LAYER>
__global__ void aggregate(float* __restrict__ outExt) {
    constexpr int LANES = F / 4;    // 24 (F=96) or 16 (F=64)
    int warp = blockIdx.x * (blockDim.x >> 5) + (threadIdx.x >> 5);
    if (warp >= NN) return;
    int lane = threadIdx.x & 31;
    const uint2* __restrict__ xwb = reinterpret_cast<const uint2*>(g_xwb);
    float* __restrict__ out = TO_H ? (float*)g_h : outExt;
    bool active = lane < LANES;

    float acc[4] = {0.f, 0.f, 0.f, 0.f};

    int s = g_rowptr[warp], t = g_rowptr[warp + 1];
    int e = s;
    for (; e + 4 <= t; e += 4) {
        int   s0 = __ldg(&g_src[e]);
        int   s1 = __ldg(&g_src[e + 1]);
        int   s2 = __ldg(&g_src[e + 2]);
        int   s3 = __ldg(&g_src[e + 3]);
        float n0 = __ldg(&g_norm[e]);
        float n1 = __ldg(&g_norm[e + 1]);
        float n2 = __ldg(&g_norm[e + 2]);
        float n3 = __ldg(&g_norm[e + 3]);
        if (active) {
            uint2 v0 = xwb[(size_t)s0 * LANES + lane];
            uint2 v1 = xwb[(size_t)s1 * LANES + lane];
            uint2 v2 = xwb[(size_t)s2 * LANES + lane];
            uint2 v3 = xwb[(size_t)s3 * LANES + lane];
            bf16_fma4(acc, v0, n0);
            bf16_fma4(acc, v1, n1);
            bf16_fma4(acc, v2, n2);
            bf16_fma4(acc, v3, n3);
        }
    }
    for (; e < t; ++e) {
        int   s0 = __ldg(&g_src[e]);
        float n0 = __ldg(&g_norm[e]);
        if (active) {
            uint2 v0 = xwb[(size_t)s0 * LANES + lane];
            bf16_fma4(acc, v0, n0);
        }
    }

    float d = g_dis[warp];
    float sn = d * d;
    if (active) {
        uint2 v = xwb[(size_t)warp * LANES + lane];
        bf16_fma4(acc, v, sn);

        int f0 = lane * 4;
        float4 r;
        r.x = acc[0] * g_sc[LAYER][f0 + 0] + g_sh[LAYER][f0 + 0];
        r.y = acc[1] * g_sc[LAYER][f0 + 1] + g_sh[LAYER][f0 + 1];
        r.z = acc[2] * g_sc[LAYER][f0 + 2] + g_sh[LAYER][f0 + 2];
        r.w = acc[3] * g_sc[LAYER][f0 + 3] + g_sh[LAYER][f0 + 3];
        if (RELU) {
            r.x = fmaxf(r.x, 0.f); r.y = fmaxf(r.y, 0.f);
            r.z = fmaxf(r.z, 0.f); r.w = fmaxf(r.w, 0.f);
        }
        *reinterpret_cast<float4*>(&out[(size_t)warp * F + f0]) = r;
    }
}

// ----------------------------------------------------------------------------
// Launch — 7 kernel launches, graph-capturable.
// ----------------------------------------------------------------------------
extern "C" void kernel_launch(void* const* d_in, const int* in_sizes, int n_in,
                              void* d_out, int out_size) {
    const float* x   = (const float*)d_in[0];
    const int*   ei  = (const int*)d_in[1];       // int32 (JAX x64 disabled)
    const float* ew  = (const float*)d_in[2];
    const float* W1  = (const float*)d_in[3];
    const float* b1  = (const float*)d_in[4];
    const float* W2  = (const float*)d_in[5];
    const float* b2  = (const float*)d_in[6];
    const float* W3  = (const float*)d_in[7];
    const float* b3  = (const float*)d_in[8];
    const float* g1  = (const float*)d_in[9];
    const float* be1 = (const float*)d_in[10];
    const float* m1  = (const float*)d_in[11];
    const float* v1  = (const float*)d_in[12];
    const float* g2  = (const float*)d_in[13];
    const float* be2 = (const float*)d_in[14];
    const float* m2  = (const float*)d_in[15];
    const float* v2  = (const float*)d_in[16];
    float* out = (float*)d_out;

    build_graph<<<GRID_NB, 1024>>>(ei, ew,
                                   g1, be1, m1, v1, b1,
                                   g2, be2, m2, v2, b2, b3);

    const int gemmBlocks = (NN + 127) / 128;   // 391
    const int aggBlocks  = (NN + 15) / 16;     // 16 warps/block of 512

    gemm_tc<FIN, FH, false><<<gemmBlocks, 256>>>(x, W1);
    aggregate<FH, true, true, 0><<<aggBlocks, 512>>>(nullptr);

    gemm_tc<FH, FH, true><<<gemmBlocks, 256>>>(nullptr, W2);
    aggregate<FH, true, true, 1><<<aggBlocks, 512>>>(nullptr);

    gemm_tc<FH, FOUT, true><<<gemmBlocks, 256>>>(nullptr, W3);
    aggregate<FOUT, false, false, 2><<<aggBlocks, 512>>>(out);
}

// round 15
// speedup vs baseline: 1.1969x; 1.0137x over previous
#include <cuda_runtime.h>
#include <cuda_bf16.h>
#include <cstdint>

#define NN 50000
#define EE 800000
#define FIN 128
#define FH 96
#define FOUT 64
#define BN_EPS 1e-5f
#define SCAN_NB 49            // ceil(50000/1024) -- scan-participating blocks
#define GRID_NB 148           // one block per SM; all resident -> barrier safe

// ----------------------------------------------------------------------------
// Device scratch (static; no cudaMalloc anywhere).
// build_graph is fully self-contained: leaves g_deg/g_cnt/g_scanstate and the
// barrier state zeroed for the next call. First call sees load-time zeros.
// ----------------------------------------------------------------------------
__device__ float g_deg[NN];
__device__ float g_dis[NN];
__device__ int   g_cnt[NN];
__device__ int   g_cursor[NN];
__device__ unsigned long long g_scanstate[SCAN_NB];
__device__ int   g_bar_count;
__device__ volatile int g_bar_sense;
__device__ int   g_rowptr[NN + 1];
__device__ int   g_src[EE];
__device__ float g_norm[EE];
__device__ uint32_t g_xwb[(size_t)NN * FH / 2];   // GEMM output, bf16x2 packed
__device__ float g_h[(size_t)NN * FH];            // activation buffer (fp32)
__device__ float g_sc[3][FH];
__device__ float g_sh[3][FH];

// ----------------------------------------------------------------------------
// Self-resetting sense-reversing grid barrier (all GRID_NB blocks resident).
// ----------------------------------------------------------------------------
__device__ __forceinline__ void grid_barrier(int* sense_local) {
    __syncthreads();
    if (threadIdx.x == 0) {
        int s = *sense_local ^ 1;
        *sense_local = s;
        __threadfence();
        if (atomicAdd(&g_bar_count, 1) == GRID_NB - 1) {
            g_bar_count = 0;
            __threadfence();
            g_bar_sense = s;
        } else {
            while (g_bar_sense != s) __nanosleep(64);
        }
    }
    __syncthreads();
}

// ----------------------------------------------------------------------------
// Fused graph build, 148 blocks x 1024 threads (full chip on edge phases).
// ----------------------------------------------------------------------------
#define FLAG_AGG (1ULL << 62)
#define FLAG_INC (2ULL << 62)
#define VAL_MASK 0xffffffffULL

__global__ void __launch_bounds__(1024, 1)
build_graph(const int* __restrict__ ei, const float* __restrict__ ew,
            const float* g1, const float* be1, const float* m1, const float* v1, const float* b1,
            const float* g2, const float* be2, const float* m2, const float* v2, const float* b2,
            const float* b3) {
    int tid = threadIdx.x, bid = blockIdx.x;
    int gid = bid * 1024 + tid;
    const int GSTR = GRID_NB * 1024;
    int sense = 0;

    // Folded affine params (block 0, disjoint thread ranges)
    if (bid == 0) {
        if (tid < FH) {
            int f = tid;
            float a = g1[f] * rsqrtf(v1[f] + BN_EPS);
            g_sc[0][f] = a;
            g_sh[0][f] = (b1[f] - m1[f]) * a + be1[f];
        } else if (tid >= 128 && tid < 128 + FH) {
            int f = tid - 128;
            float a = g2[f] * rsqrtf(v2[f] + BN_EPS);
            g_sc[1][f] = a;
            g_sh[1][f] = (b2[f] - m2[f]) * a + be2[f];
        } else if (tid >= 256 && tid < 256 + FOUT) {
            int f = tid - 256;
            g_sc[2][f] = 1.0f;
            g_sh[2][f] = b3[f];
        }
    }

    // Phase A: degree accumulation, full chip
    for (int e = gid; e < EE; e += GSTR) {
        int c = ei[EE + e];
        atomicAdd(&g_deg[c], ew[e]);
        atomicAdd(&g_cnt[c], 1);
    }
    grid_barrier(&sense);

    // Phase B: blocks 0..48 do the node scan; others wait at the barrier
    if (bid < SCAN_NB) {
        __shared__ int sh[1024];
        __shared__ int s_prefix;
        int i = bid * 1024 + tid;
        int v = (i < NN) ? g_cnt[i] : 0;
        sh[tid] = v;
        __syncthreads();
#pragma unroll
        for (int off = 1; off < 1024; off <<= 1) {
            int t = (tid >= off) ? sh[tid - off] : 0;
            __syncthreads();
            sh[tid] += t;
            __syncthreads();
        }
        int total = sh[1023];
        if (tid == 0) {
            if (bid == 0) {
                s_prefix = 0;
                atomicExch(&g_scanstate[0], FLAG_INC | (unsigned long long)total);
                g_rowptr[NN] = EE;
            } else {
                atomicExch(&g_scanstate[bid], FLAG_AGG | (unsigned long long)total);
                int p = bid - 1;
                long long prefix = 0;
                while (true) {
                    unsigned long long s = *(volatile unsigned long long*)&g_scanstate[p];
                    unsigned long long flag = s & (3ULL << 62);
                    if (flag == FLAG_INC) { prefix += (long long)(s & VAL_MASK); break; }
                    if (flag == FLAG_AGG) { prefix += (long long)(s & VAL_MASK); --p; }
                    else __nanosleep(32);
                }
                atomicExch(&g_scanstate[bid], FLAG_INC | (unsigned long long)(prefix + total));
                s_prefix = (int)prefix;
            }
        }
        __syncthreads();
        if (i < NN) {
            g_rowptr[i] = s_prefix + sh[tid] - v;
            g_dis[i] = rsqrtf(g_deg[i] + 1.0f);   // self-loop weight 1 => deg>0
            g_cursor[i] = 0;                       // ready for phase C
        }
    }
    grid_barrier(&sense);

    // Phase C: fill CSR, full chip + restore zero-state
    for (int e = gid; e < EE; e += GSTR) {
        int r = ei[e];
        int c = ei[EE + e];
        float nrm = g_dis[r] * ew[e] * g_dis[c];
        int pos = g_rowptr[c] + atomicAdd(&g_cursor[c], 1);
        g_src[pos] = r;
        g_norm[pos] = nrm;
    }
    if (bid < SCAN_NB) {
        int i = bid * 1024 + tid;
        if (i < NN) { g_deg[i] = 0.f; g_cnt[i] = 0; }
        if (tid == 0) g_scanstate[bid] = 0ULL;
    }
}

// ----------------------------------------------------------------------------
// tf32 tensor-core GEMM with cp.async double buffering.
// BM=128, BK=32 (dynamic smem, fewer pipeline stages), 256 threads
// (4 M-warps x 2 N-warps), 3 blocks/SM. smem [buf][m][k] stride 36:
// fragment column loads hit 32 distinct banks; rows 16B-aligned for cp.async.
// Output packed bf16x2 into g_xwb.
// ----------------------------------------------------------------------------
__device__ __forceinline__ float f2tf32(float x) {
    uint32_t r;
    asm("cvt.rna.tf32.f32 %0, %1;" : "=r"(r) : "f"(x));
    float out;
    asm("mov.b32 %0, %1;" : "=f"(out) : "r"(r));
    return out;
}

__device__ __forceinline__ uint32_t packbf(float lo, float hi) {
    __nv_bfloat162 h = __floats2bfloat162_rn(lo, hi);   // .x = lo (low half)
    return *reinterpret_cast<uint32_t*>(&h);
}

__device__ __forceinline__ void cp_async16(uint32_t saddr, const void* gptr) {
    asm volatile("cp.async.cg.shared.global [%0], [%1], 16;" :: "r"(saddr), "l"(gptr));
}
__device__ __forceinline__ void cp_commit() {
    asm volatile("cp.async.commit_group;");
}
template <int N>
__device__ __forceinline__ void cp_wait() {
    asm volatile("cp.async.wait_group %0;" :: "n"(N));
}

template <int KDIM, int BN, bool FROM_H>
__global__ void __launch_bounds__(256, 3) gemm_tc(const float* __restrict__ Xext,
                                                  const float* __restrict__ W) {
    constexpr int BM = 128, BK = 32;
    constexpr int WN = BN / 2;          // 48 or 32
    constexpr int NF = WN / 8;          // 6 or 4
    constexpr int KT = KDIM / BK;       // 4 (K=128) or 3 (K=96)
    constexpr int STR = BK + 4;         // 36 floats; 144B rows (16B aligned)
    constexpr int KD4 = KDIM / 4;
    constexpr int NAQ = BM * (BK / 4);  // A float4s per tile (1024)
    constexpr int NBQ = BN * (BK / 4);  // B float4s per tile (768 or 512)

    const float* __restrict__ X = FROM_H ? (const float*)g_h : Xext;

    extern __shared__ float smem[];
    float (*As)[BM][STR] = reinterpret_cast<float (*)[BM][STR]>(smem);
    float (*Bs)[BN][STR] = reinterpret_cast<float (*)[BN][STR]>(smem + 2 * BM * STR);

    int tid = threadIdx.x;
    int wid = tid >> 5, lane = tid & 31;
    int wm = wid & 3, wn = wid >> 2;
    int g = lane >> 2, tig = lane & 3;
    int row0 = blockIdx.x * BM;
    int m0 = wm * 32;
    int n0 = wn * WN;

    float acc[2][NF][4];
#pragma unroll
    for (int mi = 0; mi < 2; ++mi)
#pragma unroll
        for (int ni = 0; ni < NF; ++ni)
#pragma unroll
            for (int c = 0; c < 4; ++c) acc[mi][ni][c] = 0.f;

    const float4* __restrict__ X4 = reinterpret_cast<const float4*>(X);
    const float4* __restrict__ W4 = reinterpret_cast<const float4*>(W);

    auto issue_tile = [&](int kt, int buf) {
        int kb4 = kt * (BK / 4);
#pragma unroll
        for (int t = 0; t < NAQ / 256; ++t) {       // 4 iterations
            int idx = tid + t * 256;                 // 0..1023
            int m = idx >> 3, kq = idx & 7;          // 8 float4 per 32-float row
            int r = row0 + m;
            if (r < NN) {
                uint32_t dst = (uint32_t)__cvta_generic_to_shared(&As[buf][m][kq * 4]);
                cp_async16(dst, &X4[(size_t)r * KD4 + kb4 + kq]);
            }
        }
#pragma unroll
        for (int t = 0; t < (NBQ + 255) / 256; ++t) {
            int idx = tid + t * 256;
            if (idx < NBQ) {
                int f = idx >> 3, kq = idx & 7;
                uint32_t dst = (uint32_t)__cvta_generic_to_shared(&Bs[buf][f][kq * 4]);
                cp_async16(dst, &W4[(size_t)f * KD4 + kb4 + kq]);
            }
        }
    };

    issue_tile(0, 0);
    cp_commit();

    for (int kt = 0; kt < KT; ++kt) {
        int cur = kt & 1;
        if (kt + 1 < KT) {
            issue_tile(kt + 1, cur ^ 1);
            cp_commit();
            cp_wait<1>();
        } else {
            cp_wait<0>();
        }
        __syncthreads();

#pragma unroll
        for (int kf = 0; kf < BK / 8; ++kf) {       // 4 fragment steps per tile
            int kb = kf * 8;
            uint32_t a[2][4];
#pragma unroll
            for (int mi = 0; mi < 2; ++mi) {
                int mb = m0 + mi * 16;
                a[mi][0] = __float_as_uint(f2tf32(As[cur][mb + g][kb + tig]));
                a[mi][1] = __float_as_uint(f2tf32(As[cur][mb + g + 8][kb + tig]));
                a[mi][2] = __float_as_uint(f2tf32(As[cur][mb + g][kb + tig + 4]));
                a[mi][3] = __float_as_uint(f2tf32(As[cur][mb + g + 8][kb + tig + 4]));
            }
            uint32_t b[NF][2];
#pragma unroll
            for (int ni = 0; ni < NF; ++ni) {
                int nb = n0 + ni * 8;
                b[ni][0] = __float_as_uint(f2tf32(Bs[cur][nb + g][kb + tig]));
                b[ni][1] = __float_as_uint(f2tf32(Bs[cur][nb + g][kb + tig + 4]));
            }
#pragma unroll
            for (int mi = 0; mi < 2; ++mi)
#pragma unroll
                for (int ni = 0; ni < NF; ++ni) {
                    asm volatile(
                        "mma.sync.aligned.m16n8k8.row.col.f32.tf32.tf32.f32 "
                        "{%0,%1,%2,%3},{%4,%5,%6,%7},{%8,%9},{%0,%1,%2,%3};"
                        : "+f"(acc[mi][ni][0]), "+f"(acc[mi][ni][1]),
                          "+f"(acc[mi][ni][2]), "+f"(acc[mi][ni][3])
                        : "r"(a[mi][0]), "r"(a[mi][1]), "r"(a[mi][2]), "r"(a[mi][3]),
                          "r"(b[ni][0]), "r"(b[ni][1]));
                }
        }
        __syncthreads();
    }

    // Epilogue: pack column pairs to bf16x2, one uint32 store each.
#pragma unroll
    for (int mi = 0; mi < 2; ++mi) {
        int r0 = row0 + m0 + mi * 16 + g;
        int r1 = r0 + 8;
#pragma unroll
        for (int ni = 0; ni < NF; ++ni) {
            int c = n0 + ni * 8 + tig * 2;
            if (r0 < NN)
                g_xwb[(size_t)r0 * (BN / 2) + (c >> 1)] = packbf(acc[mi][ni][0], acc[mi][ni][1]);
            if (r1 < NN)
                g_xwb[(size_t)r1 * (BN / 2) + (c >> 1)] = packbf(acc[mi][ni][2], acc[mi][ni][3]);
        }
    }
}

// ----------------------------------------------------------------------------
// CSR aggregation over bf16 features. One warp/node. Lanes 0..F/4-1 each
// hold 4 features (one uint2 = 2x bf16x2). No shfl: edge indices/weights are
// warp-uniform broadcast loads. Unroll-4 over edges -> 4 gathers in flight.
// fp32 accumulation. 512-thread blocks.
// ----------------------------------------------------------------------------
__device__ __forceinline__ void bf16_fma4(float* acc, uint2 v, float n) {
    __nv_bfloat162 p0 = *reinterpret_cast<__nv_bfloat162*>(&v.x);
    __nv_bfloat162 p1 = *reinterpret_cast<__nv_bfloat162*>(&v.y);
    float2 f0 = __bfloat1622float2(p0);
    float2 f1 = __bfloat1622float2(p1);
    acc[0] += n * f0.x;
    acc[1] += n * f0.y;
    acc[2] += n * f1.x;
    acc[3] += n * f1.y;
}

template <int F, bool RELU, bool TO_H, int LAYER>
__global__ void aggregate(float* __restrict__ outExt) {
    constexpr int LANES = F / 4;    // 24 (F=96) or 16 (F=64)
    int warp = blockIdx.x * (blockDim.x >> 5) + (threadIdx.x >> 5);
    if (warp >= NN) return;
    int lane = threadIdx.x & 31;
    const uint2* __restrict__ xwb = reinterpret_cast<const uint2*>(g_xwb);
    float* __restrict__ out = TO_H ? (float*)g_h : outExt;
    bool active = lane < LANES;

    float acc[4] = {0.f, 0.f, 0.f, 0.f};

    int s = g_rowptr[warp], t = g_rowptr[warp + 1];
    int e = s;
    for (; e + 4 <= t; e += 4) {
        int   s0 = __ldg(&g_src[e]);
        int   s1 = __ldg(&g_src[e + 1]);
        int   s2 = __ldg(&g_src[e + 2]);
        int   s3 = __ldg(&g_src[e + 3]);
        float n0 = __ldg(&g_norm[e]);
        float n1 = __ldg(&g_norm[e + 1]);
        float n2 = __ldg(&g_norm[e + 2]);
        float n3 = __ldg(&g_norm[e + 3]);
        if (active) {
            uint2 v0 = xwb[(size_t)s0 * LANES + lane];
            uint2 v1 = xwb[(size_t)s1 * LANES + lane];
            uint2 v2 = xwb[(size_t)s2 * LANES + lane];
            uint2 v3 = xwb[(size_t)s3 * LANES + lane];
            bf16_fma4(acc, v0, n0);
            bf16_fma4(acc, v1, n1);
            bf16_fma4(acc, v2, n2);
            bf16_fma4(acc, v3, n3);
        }
    }
    for (; e < t; ++e) {
        int   s0 = __ldg(&g_src[e]);
        float n0 = __ldg(&g_norm[e]);
        if (active) {
            uint2 v0 = xwb[(size_t)s0 * LANES + lane];
            bf16_fma4(acc, v0, n0);
        }
    }

    float d = g_dis[warp];
    float sn = d * d;
    if (active) {
        uint2 v = xwb[(size_t)warp * LANES + lane];
        bf16_fma4(acc, v, sn);

        int f0 = lane * 4;
        float4 r;
        r.x = acc[0] * g_sc[LAYER][f0 + 0] + g_sh[LAYER][f0 + 0];
        r.y = acc[1] * g_sc[LAYER][f0 + 1] + g_sh[LAYER][f0 + 1];
        r.z = acc[2] * g_sc[LAYER][f0 + 2] + g_sh[LAYER][f0 + 2];
        r.w = acc[3] * g_sc[LAYER][f0 + 3] + g_sh[LAYER][f0 + 3];
        if (RELU) {
            r.x = fmaxf(r.x, 0.f); r.y = fmaxf(r.y, 0.f);
            r.z = fmaxf(r.z, 0.f); r.w = fmaxf(r.w, 0.f);
        }
        *reinterpret_cast<float4*>(&out[(size_t)warp * F + f0]) = r;
    }
}

// ----------------------------------------------------------------------------
// Launch — 7 kernel launches, graph-capturable. cudaFuncSetAttribute is an
// immediate (non-stream) call: capture-safe, no allocation.
// ----------------------------------------------------------------------------
extern "C" void kernel_launch(void* const* d_in, const int* in_sizes, int n_in,
                              void* d_out, int out_size) {
    const float* x   = (const float*)d_in[0];
    const int*   ei  = (const int*)d_in[1];       // int32 (JAX x64 disabled)
    const float* ew  = (const float*)d_in[2];
    const float* W1  = (const float*)d_in[3];
    const float* b1  = (const float*)d_in[4];
    const float* W2  = (const float*)d_in[5];
    const float* b2  = (const float*)d_in[6];
    const float* W3  = (const float*)d_in[7];
    const float* b3  = (const float*)d_in[8];
    const float* g1  = (const float*)d_in[9];
    const float* be1 = (const float*)d_in[10];
    const float* m1  = (const float*)d_in[11];
    const float* v1  = (const float*)d_in[12];
    const float* g2  = (const float*)d_in[13];
    const float* be2 = (const float*)d_in[14];
    const float* m2  = (const float*)d_in[15];
    const float* v2  = (const float*)d_in[16];
    float* out = (float*)d_out;

    // Dynamic smem sizes: (2*BM + 2*BN) * 36 floats
    const int smem96 = (2 * 128 + 2 * 96) * 36 * 4;   // 64512 B
    const int smem64 = (2 * 128 + 2 * 64) * 36 * 4;   // 55296 B
    cudaFuncSetAttribute(gemm_tc<FIN, FH, false>,
                         cudaFuncAttributeMaxDynamicSharedMemorySize, smem96);
    cudaFuncSetAttribute(gemm_tc<FH, FH, true>,
                         cudaFuncAttributeMaxDynamicSharedMemorySize, smem96);
    cudaFuncSetAttribute(gemm_tc<FH, FOUT, true>,
                         cudaFuncAttributeMaxDynamicSharedMemorySize, smem64);

    build_graph<<<GRID_NB, 1024>>>(ei, ew,
                                   g1, be1, m1, v1, b1,
                                   g2, be2, m2, v2, b2, b3);

    const int gemmBlocks = (NN + 127) / 128;   // 391
    const int aggBlocks  = (NN + 15) / 16;     // 16 warps/block of 512

    gemm_tc<FIN, FH, false><<<gemmBlocks, 256, smem96>>>(x, W1);
    aggregate<FH, true, true, 0><<<aggBlocks, 512>>>(nullptr);

    gemm_tc<FH, FH, true><<<gemmBlocks, 256, smem96>>>(nullptr, W2);
    aggregate<FH, true, true, 1><<<aggBlocks, 512>>>(nullptr);

    gemm_tc<FH, FOUT, true><<<gemmBlocks, 256, smem64>>>(nullptr, W3);
    aggregate<FOUT, false, false, 2><<<aggBlocks, 512>>>(out);
}